// round 8
// baseline (speedup 1.0000x reference)
#include <cuda_runtime.h>
#include <cstdint>

#define AA 200000
#define BB 8
#define GG 64
#define KK 4
#define TILE 1024
#define NT 196            // 196*1024 = 200704 >= AA
#define CAP 200704
typedef unsigned long long u64;
typedef unsigned int u32;

// ---- device scratch (static: no allocation allowed) ----
__device__ u64 g_key[BB][AA];                 // per-anchor (mv_bits<<32)|(63-argmax_g)
__device__ u64 g_part[(size_t)BB*GG*NT*4];    // per-tile top-4 partials
__device__ u64 g_top[BB*GG*4];                // global top-4 per (b,g)
__device__ u64 g_poskey[BB][CAP];             // (r_bits<<32)|anchor for positives
__device__ int g_posg[BB][CAP];               // matches[] of each positive
__device__ int g_poscnt[BB];
__device__ int g_counts[BB][GG];

// ---- JAX threefry2x32 (exact) ----
__device__ __forceinline__ u32 rotl32(u32 v,int d){return (v<<d)|(v>>(32-d));}
__device__ __forceinline__ void threefry(u32 k0,u32 k1,u32 x0,u32 x1,u32&o0,u32&o1){
  u32 k2=k0^k1^0x1BD11BDAu;
  x0+=k0; x1+=k1;
#define R4(a,b,c,d) x0+=x1;x1=rotl32(x1,a);x1^=x0; x0+=x1;x1=rotl32(x1,b);x1^=x0; \
                    x0+=x1;x1=rotl32(x1,c);x1^=x0; x0+=x1;x1=rotl32(x1,d);x1^=x0;
  R4(13,15,26,6)  x0+=k1;x1+=k2+1u;
  R4(17,29,16,24) x0+=k2;x1+=k0+2u;
  R4(13,15,26,6)  x0+=k0;x1+=k1+3u;
  R4(17,29,16,24) x0+=k1;x1+=k2+4u;
  R4(13,15,26,6)  o0=x0+k2; o1=x1+k0+5u;
#undef R4
}
// keys[b] of jax.random.split(jax.random.key(42), 8), PARTITIONABLE threefry:
// child b = full cipher output of threefry(key=(0,42), counter=(0,b))
__device__ __forceinline__ void image_key(int b,u32&k0,u32&k1){
  threefry(0u,42u,0u,(u32)b,k0,k1);
}
// selection key: (bits(uniform r)<<32)|anchor ; ascending == stable double-argsort rank
// PARTITIONABLE random_bits(32): counter (0,a), word = o0 ^ o1
__device__ __forceinline__ u64 rank_key(u32 k0,u32 k1,int a){
  u32 y0,y1; threefry(k0,k1,0u,(u32)a,y0,y1);
  u32 bits=y0^y1;
  float r=__uint_as_float((bits>>9)|0x3F800000u)-1.0f;
  return (((u64)__float_as_uint(r))<<32)|(u32)a;
}
__device__ __forceinline__ void ins4(u64&t0,u64&t1,u64&t2,u64&t3,u64 k){
  if(k>t3){ t3=k; u64 tm;
    if(t3>t2){tm=t2;t2=t3;t3=tm;}
    if(t2>t1){tm=t1;t1=t2;t2=tm;}
    if(t1>t0){tm=t0;t0=t1;t1=tm;} }
}

// ---- main fused pass: IoU once, both reductions ----
__global__ void __launch_bounds__(256) k_main(const float* __restrict__ anchors,
                                              const float* __restrict__ gts){
  __shared__ float4 sA[TILE];
  __shared__ float  sAar[TILE];
  __shared__ u64    sHalf[TILE][2];
  __shared__ float4 sG[GG];
  __shared__ float  sGar[GG];
  __shared__ u64    sTop[GG][4][4];
  int tile=blockIdx.x, b=blockIdx.y, tid=threadIdx.x;
  int g=tid&63, s=tid>>6, hp=(tid>>5)&1, lane=tid&31;
  if(tid<GG){
    const float* p=gts+((size_t)b*GG+tid)*4;
    float cx=p[0],cy=p[1],w=p[2],h=p[3];
    float x0=__fsub_rn(cx,__fmul_rn(0.5f,w)),y0=__fsub_rn(cy,__fmul_rn(0.5f,h));
    float x1=__fadd_rn(cx,__fmul_rn(0.5f,w)),y1=__fadd_rn(cy,__fmul_rn(0.5f,h));
    sG[tid]=make_float4(x0,y0,x1,y1);
    sGar[tid]=__fmul_rn(__fsub_rn(x1,x0),__fsub_rn(y1,y0));
  }
  int aBase=tile*TILE;
  for(int j=0;j<4;j++){
    int al=tid+j*256, a=aBase+al;
    if(a<AA){
      const float* p=anchors+((size_t)b*AA+a)*4;
      float cx=p[0],cy=p[1],w=p[2],h=p[3];
      float x0=__fsub_rn(cx,__fmul_rn(0.5f,w)),y0=__fsub_rn(cy,__fmul_rn(0.5f,h));
      float x1=__fadd_rn(cx,__fmul_rn(0.5f,w)),y1=__fadd_rn(cy,__fmul_rn(0.5f,h));
      sA[al]=make_float4(x0,y0,x1,y1);
      sAar[al]=__fmul_rn(__fsub_rn(x1,x0),__fsub_rn(y1,y0));
    } else { sA[al]=make_float4(9e9f,9e9f,9e9f,9e9f); sAar[al]=1.0f; }
  }
  __syncthreads();
  float4 G4=sG[g]; float ga=sGar[g];
  u64 t0=0,t1=0,t2=0,t3=0;
  for(int i=0;i<256;i++){
    int al=s*256+i;
    float4 A4=sA[al]; float aa=sAar[al];
    float ltx=fmaxf(G4.x,A4.x),lty=fmaxf(G4.y,A4.y);
    float rbx=fminf(G4.z,A4.z),rby=fminf(G4.w,A4.w);
    float ww=fmaxf(__fsub_rn(rbx,ltx),0.0f),hh=fmaxf(__fsub_rn(rby,lty),0.0f);
    float inter=__fmul_rn(ww,hh);
    float uni=__fsub_rn(__fadd_rn(ga,aa),inter);
    float iou=__fdiv_rn(inter,uni);
    u32 vb=__float_as_uint(iou);
    ins4(t0,t1,t2,t3, (((u64)vb)<<32)|(u32)(~(u32)(aBase+al)));   // top-k key
    u32 m=__reduce_max_sync(0xffffffffu,vb);                       // per-anchor half-max
    u32 bal=__ballot_sync(0xffffffffu,vb==m);
    if(lane==0){
      int wl=__ffs(bal)-1;                                         // lowest g wins ties
      sHalf[al][hp]=(((u64)m)<<32)|(u32)(63-(hp*32+wl));
    }
  }
  __syncthreads();
  u32 rk0,rk1; image_key(b,rk0,rk1);
  for(int j=0;j<4;j++){
    int al=tid*4+j, a=aBase+al;
    if(a<AA){
      u64 kA=sHalf[al][0],kB=sHalf[al][1];
      u64 km=kA>kB?kA:kB;
      g_key[b][a]=km;
      if((km>>32)>=0x3F333333ull){                                 // mv >= 0.7f
        int slot=atomicAdd(&g_poscnt[b],1);
        g_poskey[b][slot]=rank_key(rk0,rk1,a);
        g_posg[b][slot]=63-(int)(km&0xFFFFFFFFull);
      }
    }
  }
  sTop[g][s][0]=t0; sTop[g][s][1]=t1; sTop[g][s][2]=t2; sTop[g][s][3]=t3;
  __syncthreads();
  if(tid<GG){
    u64 m0=sTop[tid][0][0],m1=sTop[tid][0][1],m2=sTop[tid][0][2],m3=sTop[tid][0][3];
    for(int ss=1;ss<4;ss++) for(int kk=0;kk<4;kk++) ins4(m0,m1,m2,m3,sTop[tid][ss][kk]);
    size_t base=(((size_t)b*GG+tid)*NT+tile)*4;
    g_part[base]=m0; g_part[base+1]=m1; g_part[base+2]=m2; g_part[base+3]=m3;
  }
}

// ---- merge per-tile partials -> global top-4 ----
__global__ void __launch_bounds__(128) k_merge(){
  int g=blockIdx.x,b=blockIdx.y,tid=threadIdx.x;
  const u64* part=&g_part[(((size_t)b*GG+g)*NT)*4];
  u64 t0=0,t1=0,t2=0,t3=0;
  for(int i=tid;i<NT*4;i+=128) ins4(t0,t1,t2,t3,part[i]);
  __shared__ u64 sh[128][4];
  sh[tid][0]=t0;sh[tid][1]=t1;sh[tid][2]=t2;sh[tid][3]=t3;
  __syncthreads();
  if(tid==0){
    u64 m0=sh[0][0],m1=sh[0][1],m2=sh[0][2],m3=sh[0][3];
    for(int i=1;i<128;i++){
      ins4(m0,m1,m2,m3,sh[i][0]); ins4(m0,m1,m2,m3,sh[i][1]);
      ins4(m0,m1,m2,m3,sh[i][2]); ins4(m0,m1,m2,m3,sh[i][3]);
    }
    size_t o=((size_t)b*GG+g)*4;
    g_top[o]=m0;g_top[o+1]=m1;g_top[o+2]=m2;g_top[o+3]=m3;
  }
}

// ---- low-quality matches: top-4 entries tying row max, dedup, append ----
__global__ void __launch_bounds__(256) k_lowq(){
  int b=blockIdx.x,tid=threadIdx.x;
  int g=tid>>2,k=tid&3;
  __shared__ u32 cand[256];
  size_t o=((size_t)b*GG+g)*4;
  u64 key=g_top[o+k];
  u64 hq=g_top[o]>>32;
  u32 a=0xFFFFFFFFu;
  if((key>>32)==hq){
    u32 idx=~(u32)(key&0xFFFFFFFFull);
    if((g_key[b][idx]>>32)<0x3F333333ull) a=idx;   // not already threshold-positive
  }
  cand[tid]=a;
  __syncthreads();
  bool keep=(a!=0xFFFFFFFFu);
  if(keep){ for(int j=0;j<tid;j++) if(cand[j]==a){keep=false;break;} }
  if(keep){
    u32 rk0,rk1; image_key(b,rk0,rk1);
    int slot=atomicAdd(&g_poscnt[b],1);
    g_poskey[b][slot]=rank_key(rk0,rk1,(int)a);
    g_posg[b][slot]=63-(int)(g_key[b][a]&0xFFFFFFFFull);
  }
}

// ---- radix-select 128 smallest rank keys, count per GT ----
__global__ void __launch_bounds__(1024) k_sel(){
  int b=blockIdx.x,tid=threadIdx.x;
  int P=g_poscnt[b];
  __shared__ u32 hist[256];
  __shared__ u64 s_pref; __shared__ int s_want;
  u64 thr=~0ull;
  if(P>128){
    if(tid==0){s_pref=0;s_want=128;}
    __syncthreads();
    for(int p=0;p<8;p++){
      if(tid<256) hist[tid]=0;
      __syncthreads();
      int sh=56-8*p;
      u64 pref=s_pref;
      for(int i=tid;i<P;i+=1024){
        u64 k=g_poskey[b][i];
        bool ok=(p==0)||((k>>(sh+8))==pref);
        if(ok) atomicAdd(&hist[(u32)((k>>sh)&255u)],1u);
      }
      __syncthreads();
      if(tid==0){
        int want=s_want,c=0,d=0;
        for(;d<255;d++){int hh=(int)hist[d]; if(c+hh>=want)break; c+=hh;}
        s_pref=(pref<<8)|(u32)d; s_want=want-c;
      }
      __syncthreads();
    }
    thr=s_pref;   // exact 128th-smallest key (keys unique: anchor id embedded)
  }
  __shared__ int cnt[GG];
  if(tid<GG)cnt[tid]=0;
  __syncthreads();
  for(int i=tid;i<P;i+=1024){
    if(P<=128||g_poskey[b][i]<=thr) atomicAdd(&cnt[g_posg[b][i]],1);
  }
  __syncthreads();
  if(tid<GG) g_counts[b][tid]=cnt[tid];
}

// ---- emit padded outputs: [pr | gt | valid | scores], each [B,256], float32 ----
__global__ void __launch_bounds__(256) k_emit(float* out){
  int b=blockIdx.x,tid=threadIdx.x;
  int g=tid>>2,k=tid&3;
  u64 key=g_top[((size_t)b*GG+g)*4+k];
  int idx=(int)(~(u32)(key&0xFFFFFFFFull));
  float val=__uint_as_float((u32)(key>>32));
  int c=g_counts[b][g]; if(c>KK)c=KK;
  bool v=(k<c);
  int o=b*256+tid;
  out[o]        = v?(float)idx:-1.0f;
  out[2048+o]   = v?(float)g :-1.0f;
  out[4096+o]   = v?1.0f:0.0f;
  out[6144+o]   = v?val :0.0f;
}

__global__ void k_zero(){ if(threadIdx.x<BB) g_poscnt[threadIdx.x]=0; }

extern "C" void kernel_launch(void* const* d_in, const int* in_sizes, int n_in,
                              void* d_out, int out_size){
  const float* anchors=(const float*)d_in[0];   // [B,A,4] cxcywh
  const float* gts    =(const float*)d_in[1];   // [B,G,4] cxcywh
  float* out=(float*)d_out;
  k_zero <<<1,32>>>();
  k_main <<<dim3(NT,BB),256>>>(anchors,gts);
  k_merge<<<dim3(GG,BB),128>>>();
  k_lowq <<<BB,256>>>();
  k_sel  <<<BB,1024>>>();
  k_emit <<<BB,256>>>(out);
}